// round 16
// baseline (speedup 1.0000x reference)
#include <cuda_runtime.h>
#include <math.h>

// Problem constants: B=4, N=1024, D=512, H=8, dh=64
#define NB 4
#define NN 1024
#define ND 512
#define NH 8
#define FDIM 144   // phase1 [0,72): lor features, phase2 [72,144): kin features

// ---- static scratch (no allocations allowed) ----
__device__ float g_xqkv[4096 * 1536];
__device__ float g_vqkv[4096 * 1024];
__device__ float g_Fq[32 * 1024 * FDIM];
__device__ float g_Fk[32 * 1024 * FDIM];
__device__ unsigned g_b1[1024 * 32];
__device__ unsigned g_b2[1024 * 32];
__device__ unsigned g_b3[1024 * 32];

// ---------------- topo bit kernels ----------------
__global__ void pack_kernel(const float* __restrict__ A) {
    int i = blockIdx.x, w = threadIdx.x;
    const float* row = A + (size_t)i * 1024 + w * 32;
    unsigned word = 0;
#pragma unroll
    for (int b = 0; b < 32; b++)
        if (row[b] > 0.f) word |= (1u << b);
    g_b1[i * 32 + w] = word;
}
__global__ void pow2_kernel() {
    int i = blockIdx.x, w = threadIdx.x;
    unsigned acc = 0;
    for (int kw = 0; kw < 32; kw++) {
        unsigned word = g_b1[i * 32 + kw];
        while (word) {
            int b = __ffs(word) - 1; word &= word - 1;
            acc |= g_b1[(kw * 32 + b) * 32 + w];
        }
    }
    g_b2[i * 32 + w] = acc;
}
__global__ void pow3_kernel() {
    int i = blockIdx.x, w = threadIdx.x;
    unsigned acc = 0;
    for (int kw = 0; kw < 32; kw++) {
        unsigned word = g_b2[i * 32 + kw];
        while (word) {
            int b = __ffs(word) - 1; word &= word - 1;
            acc |= g_b1[(kw * 32 + b) * 32 + w];
        }
    }
    g_b3[i * 32 + w] = acc;
}

// ---------------- 8x8 micro-kernel ----------------
#define INNER8x8(ACC, ASB, BSB)                                                \
    _Pragma("unroll")                                                          \
    for (int kk = 0; kk < 8; kk++) {                                           \
        float4 a0 = *(const float4*)&ASB[kk][ty * 8];                          \
        float4 a1 = *(const float4*)&ASB[kk][ty * 8 + 4];                      \
        float4 b0 = *(const float4*)&BSB[kk][tx * 8];                          \
        float4 b1 = *(const float4*)&BSB[kk][tx * 8 + 4];                      \
        float ar[8] = {a0.x, a0.y, a0.z, a0.w, a1.x, a1.y, a1.z, a1.w};        \
        float br[8] = {b0.x, b0.y, b0.z, b0.w, b1.x, b1.y, b1.z, b1.w};        \
        _Pragma("unroll") for (int ii = 0; ii < 8; ii++)                       \
            _Pragma("unroll") for (int jj = 0; jj < 8; jj++)                   \
                ACC[ii][jj] += ar[ii] * br[jj];                                \
    }

// ---------------- fp32 NT GEMM (128x128 tile, 8x8 micro) ----------------
// C[m][n] = sum_k A[m][k]*B[n][k] + bias[n]
__global__ __launch_bounds__(256, 2) void gemm_nt(
    const float* __restrict__ A, const float* __restrict__ Bm,
    const float* __restrict__ bias, float* __restrict__ C, int K, int ldc) {
    __shared__ float As[2][8][128];
    __shared__ float Bs[2][8][128];
    int m0 = blockIdx.y * 128, n0 = blockIdx.x * 128;
    int t = threadIdx.x;
    int am = t >> 1, af = (t & 1) * 4;      // loader: row am, k-offset af (A and B alike)
    int ty = t >> 4, tx = t & 15;
    const float* Ap = A + (size_t)(m0 + am) * K + af;
    const float* Bp = Bm + (size_t)(n0 + am) * K + af;
    float4 pa = *(const float4*)Ap;
    float4 pb = *(const float4*)Bp;
    float acc[8][8];
#pragma unroll
    for (int ii = 0; ii < 8; ii++)
#pragma unroll
        for (int jj = 0; jj < 8; jj++) acc[ii][jj] = 0.f;
    int nc = K >> 3;
    As[0][af][am] = pa.x; As[0][af + 1][am] = pa.y; As[0][af + 2][am] = pa.z; As[0][af + 3][am] = pa.w;
    Bs[0][af][am] = pb.x; Bs[0][af + 1][am] = pb.y; Bs[0][af + 2][am] = pb.z; Bs[0][af + 3][am] = pb.w;
    __syncthreads();
    for (int c = 0; c < nc; c++) {
        int cur = c & 1, nxt = cur ^ 1;
        if (c + 1 < nc) {
            pa = *(const float4*)(Ap + (c + 1) * 8);
            pb = *(const float4*)(Bp + (c + 1) * 8);
        }
        INNER8x8(acc, As[cur], Bs[cur])
        if (c + 1 < nc) {
            As[nxt][af][am] = pa.x; As[nxt][af + 1][am] = pa.y;
            As[nxt][af + 2][am] = pa.z; As[nxt][af + 3][am] = pa.w;
            Bs[nxt][af][am] = pb.x; Bs[nxt][af + 1][am] = pb.y;
            Bs[nxt][af + 2][am] = pb.z; Bs[nxt][af + 3][am] = pb.w;
            __syncthreads();
        }
    }
#pragma unroll
    for (int ii = 0; ii < 8; ii++) {
        int m = m0 + ty * 8 + ii;
#pragma unroll
        for (int jj = 0; jj < 8; jj++) {
            int n = n0 + tx * 8 + jj;
            C[(size_t)m * ldc + n] = acc[ii][jj] + bias[n];
        }
    }
}

// ---------------- feature prep: one warp per (b,h,n) ----------------
__global__ __launch_bounds__(256) void prep_kernel() {
    int gw = blockIdx.x * 8 + (threadIdx.x >> 5);
    int lane = threadIdx.x & 31;
    int n = gw & 1023;
    int bh = gw >> 10;
    int b = bh >> 3, h = bh & 7;
    const float* xrow = g_xqkv + (size_t)(b * 1024 + n) * 1536;
    const float* vrow = g_vqkv + (size_t)(b * 1024 + n) * 1024;
    float* fq = g_Fq + (size_t)(bh * 1024 + n) * FDIM;
    float* fk = g_Fk + (size_t)(bh * 1024 + n) * FDIM;
    {
        float qa = xrow[h * 64 + lane], qb = xrow[h * 64 + 32 + lane];
        float ss = qa * qa + qb * qb;
#pragma unroll
        for (int o = 16; o; o >>= 1) ss += __shfl_xor_sync(0xffffffffu, ss, o);
        float norm = sqrtf(fmaxf(ss, 1e-7f));
        float s = fminf(3.0f / norm, 1.0f);
        float m = sqrtf(fmaxf(ss * s * s, 1e-14f));
        float sc = sinhf(m) / m * s;
        if (lane == 0) fq[0] = -coshf(m);
        fq[1 + lane] = sc * qa;
        fq[33 + lane] = sc * qb;
        if (lane < 7) fq[65 + lane] = 0.f;
    }
    {
        float ka = xrow[512 + h * 64 + lane], kb = xrow[512 + h * 64 + 32 + lane];
        float ss = ka * ka + kb * kb;
#pragma unroll
        for (int o = 16; o; o >>= 1) ss += __shfl_xor_sync(0xffffffffu, ss, o);
        float norm = sqrtf(fmaxf(ss, 1e-7f));
        float s = fminf(3.0f / norm, 1.0f);
        float m = sqrtf(fmaxf(ss * s * s, 1e-14f));
        float sc = sinhf(m) / m * s;
        if (lane == 0) fk[0] = coshf(m);
        fk[1 + lane] = sc * ka;
        fk[33 + lane] = sc * kb;
        if (lane < 7) fk[65 + lane] = 0.f;
    }
    {
        float va = vrow[h * 64 + lane], vb = vrow[h * 64 + 32 + lane];
        float ss = va * va + vb * vb;
#pragma unroll
        for (int o = 16; o; o >>= 1) ss += __shfl_xor_sync(0xffffffffu, ss, o);
        if (lane == 0) { fq[72] = ss; fq[73] = 1.f; }
        fq[74 + lane] = -2.f * va;
        fq[106 + lane] = -2.f * vb;
        if (lane < 6) fq[138 + lane] = 0.f;
    }
    {
        float va = vrow[512 + h * 64 + lane], vb = vrow[512 + h * 64 + 32 + lane];
        float ss = va * va + vb * vb;
#pragma unroll
        for (int o = 16; o; o >>= 1) ss += __shfl_xor_sync(0xffffffffu, ss, o);
        if (lane == 0) { fk[72] = 1.f; fk[73] = ss; }
        fk[74 + lane] = va;
        fk[106 + lane] = vb;
        if (lane < 6) fk[138 + lane] = 0.f;
    }
}

// ---------------- score GEMM (128x128 tile, 8x8 micro, dual acc) ----------------
__global__ __launch_bounds__(256, 1) void score_kernel(
    const float* __restrict__ tau, const float* __restrict__ gamma,
    float* __restrict__ attn) {
    int bh = blockIdx.z, h = bh & 7;
    const float* A = g_Fq + (size_t)bh * NN * FDIM;
    const float* Bm = g_Fk + (size_t)bh * NN * FDIM;
    __shared__ float As[2][8][128];
    __shared__ float Bs[2][8][128];
    int i0 = blockIdx.y * 128, j0 = blockIdx.x * 128;
    int t = threadIdx.x;
    int am = t >> 1, af = (t & 1) * 4;
    int ty = t >> 4, tx = t & 15;
    const float* Ap = A + (size_t)(i0 + am) * FDIM + af;
    const float* Bp = Bm + (size_t)(j0 + am) * FDIM + af;
    float4 pa = *(const float4*)Ap;
    float4 pb = *(const float4*)Bp;
    float acc1[8][8], acc2[8][8];
#pragma unroll
    for (int ii = 0; ii < 8; ii++)
#pragma unroll
        for (int jj = 0; jj < 8; jj++) { acc1[ii][jj] = 0.f; acc2[ii][jj] = 0.f; }

    As[0][af][am] = pa.x; As[0][af + 1][am] = pa.y; As[0][af + 2][am] = pa.z; As[0][af + 3][am] = pa.w;
    Bs[0][af][am] = pb.x; Bs[0][af + 1][am] = pb.y; Bs[0][af + 2][am] = pb.z; Bs[0][af + 3][am] = pb.w;
    __syncthreads();
    for (int c = 0; c < 18; c++) {
        int cur = c & 1, nxt = cur ^ 1;
        if (c + 1 < 18) {
            pa = *(const float4*)(Ap + (c + 1) * 8);
            pb = *(const float4*)(Bp + (c + 1) * 8);
        }
        if (c < 9) {
            INNER8x8(acc1, As[cur], Bs[cur])
        } else {
            INNER8x8(acc2, As[cur], Bs[cur])
        }
        if (c + 1 < 18) {
            As[nxt][af][am] = pa.x; As[nxt][af + 1][am] = pa.y;
            As[nxt][af + 2][am] = pa.z; As[nxt][af + 3][am] = pa.w;
            Bs[nxt][af][am] = pb.x; Bs[nxt][af + 1][am] = pb.y;
            Bs[nxt][af + 2][am] = pb.z; Bs[nxt][af + 3][am] = pb.w;
            __syncthreads();
        }
    }

    float inv_tau = 1.f / fmaxf(tau[h], 1e-3f);
    float g0 = gamma[h * 3 + 0], g1 = gamma[h * 3 + 1], g2 = gamma[h * 3 + 2];
#pragma unroll
    for (int ii = 0; ii < 8; ii++) {
        int i = i0 + ty * 8 + ii;
#pragma unroll
        for (int jj = 0; jj < 8; jj++) {
            int j = j0 + tx * 8 + jj;
            int w = j >> 5, bit = j & 31;
            float st = 0.f;
            if (i != j) {
                st = g0 * (float)((g_b1[i * 32 + w] >> bit) & 1u)
                   + g1 * (float)((g_b2[i * 32 + w] >> bit) & 1u)
                   + g2 * (float)((g_b3[i * 32 + w] >> bit) & 1u);
            }
            float s = (1.f + acc1[ii][jj]) * inv_tau - fmaxf(acc2[ii][jj], 0.f) + st;
            attn[((size_t)bh * NN + i) * NN + j] = s;
        }
    }
}

// ---------------- row softmax (in place on attn) ----------------
__global__ __launch_bounds__(256) void softmax_kernel(float* __restrict__ attn) {
    float* row = attn + (size_t)blockIdx.x * 1024;
    int t = threadIdx.x;
    float4 v = reinterpret_cast<float4*>(row)[t];
    __shared__ float sm[8], ssum[8];
    float m = fmaxf(fmaxf(v.x, v.y), fmaxf(v.z, v.w));
#pragma unroll
    for (int o = 16; o; o >>= 1) m = fmaxf(m, __shfl_xor_sync(0xffffffffu, m, o));
    if ((t & 31) == 0) sm[t >> 5] = m;
    __syncthreads();
    float mx = fmaxf(fmaxf(fmaxf(sm[0], sm[1]), fmaxf(sm[2], sm[3])),
                     fmaxf(fmaxf(sm[4], sm[5]), fmaxf(sm[6], sm[7])));
    float e0 = expf(v.x - mx), e1 = expf(v.y - mx), e2 = expf(v.z - mx), e3 = expf(v.w - mx);
    float s = e0 + e1 + e2 + e3;
#pragma unroll
    for (int o = 16; o; o >>= 1) s += __shfl_xor_sync(0xffffffffu, s, o);
    if ((t & 31) == 0) ssum[t >> 5] = s;
    __syncthreads();
    float tot = ssum[0] + ssum[1] + ssum[2] + ssum[3] + ssum[4] + ssum[5] + ssum[6] + ssum[7];
    float inv = 1.f / tot;
    reinterpret_cast<float4*>(row)[t] = make_float4(e0 * inv, e1 * inv, e2 * inv, e3 * inv);
}

// ---------------- z = attn @ v_s (128x64 tile, 8x8 micro, 128 threads) ----------------
__global__ __launch_bounds__(128, 4) void zgemm_kernel(
    const float* __restrict__ attn, float* __restrict__ out) {
    int bh = blockIdx.z, b = bh >> 3, h = bh & 7;
    const float* A = attn + (size_t)bh * NN * NN;
    __shared__ float As[2][8][128];
    __shared__ float Bs[2][8][64];
    int i0 = blockIdx.y * 128;
    int t = threadIdx.x;                 // 0..127
    int d = t & 63, r = t >> 6;          // B loader: col d, row group r (0..1)
    int ty = t >> 3, tx = t & 7;         // 16 x 8 threads -> 128 x 64 tile
    const float* Ap = A + (size_t)(i0 + t) * NN;   // A loader: row t, k 0..7
    const float* Vp = g_xqkv + (size_t)(b * 1024) * 1536 + 1024 + h * 64 + d;
    float4 pa0 = *(const float4*)Ap;
    float4 pa1 = *(const float4*)(Ap + 4);
    float pb[4];
#pragma unroll
    for (int q = 0; q < 4; q++) pb[q] = Vp[(size_t)(r * 4 + q) * 1536];
    float acc[8][8];
#pragma unroll
    for (int ii = 0; ii < 8; ii++)
#pragma unroll
        for (int jj = 0; jj < 8; jj++) acc[ii][jj] = 0.f;
    As[0][0][t] = pa0.x; As[0][1][t] = pa0.y; As[0][2][t] = pa0.z; As[0][3][t] = pa0.w;
    As[0][4][t] = pa1.x; As[0][5][t] = pa1.y; As[0][6][t] = pa1.z; As[0][7][t] = pa1.w;
#pragma unroll
    for (int q = 0; q < 4; q++) Bs[0][r * 4 + q][d] = pb[q];
    __syncthreads();
    for (int c = 0; c < 128; c++) {
        int cur = c & 1, nxt = cur ^ 1;
        if (c + 1 < 128) {
            pa0 = *(const float4*)(Ap + (c + 1) * 8);
            pa1 = *(const float4*)(Ap + (c + 1) * 8 + 4);
#pragma unroll
            for (int q = 0; q < 4; q++) pb[q] = Vp[(size_t)((c + 1) * 8 + r * 4 + q) * 1536];
        }
        INNER8x8(acc, As[cur], Bs[cur])
        if (c + 1 < 128) {
            As[nxt][0][t] = pa0.x; As[nxt][1][t] = pa0.y; As[nxt][2][t] = pa0.z; As[nxt][3][t] = pa0.w;
            As[nxt][4][t] = pa1.x; As[nxt][5][t] = pa1.y; As[nxt][6][t] = pa1.z; As[nxt][7][t] = pa1.w;
#pragma unroll
            for (int q = 0; q < 4; q++) Bs[nxt][r * 4 + q][d] = pb[q];
            __syncthreads();
        }
    }
#pragma unroll
    for (int ii = 0; ii < 8; ii++) {
        int i = i0 + ty * 8 + ii;
#pragma unroll
        for (int jj = 0; jj < 8; jj++) {
            out[(size_t)(b * 1024 + i) * 512 + h * 64 + tx * 8 + jj] = acc[ii][jj];
        }
    }
}

extern "C" void kernel_launch(void* const* d_in, const int* in_sizes, int n_in,
                              void* d_out, int out_size) {
    (void)in_sizes; (void)n_in; (void)out_size;
    const float* x_tan = (const float*)d_in[0];
    const float* v_tan = (const float*)d_in[1];
    const float* topo_bias = (const float*)d_in[2];
    const float* qkv_w = (const float*)d_in[3];
    const float* qkv_b = (const float*)d_in[4];
    const float* tau = (const float*)d_in[5];
    const float* topo_gamma = (const float*)d_in[6];

    float* out = (float*)d_out;
    float* zt = out;                               // [4][1024][512]
    float* attn = out + (size_t)NB * NN * ND;      // [4][8][1024][1024]

    float *p_xqkv = nullptr, *p_vqkv = nullptr;
    cudaGetSymbolAddress((void**)&p_xqkv, g_xqkv);
    cudaGetSymbolAddress((void**)&p_vqkv, g_vqkv);

    pack_kernel<<<1024, 32>>>(topo_bias);
    pow2_kernel<<<1024, 32>>>();
    pow3_kernel<<<1024, 32>>>();

    {
        dim3 g(1536 / 128, 4096 / 128);
        gemm_nt<<<g, 256>>>(x_tan, qkv_w, qkv_b, p_xqkv, 512, 1536);
    }
    {
        dim3 g(1024 / 128, 4096 / 128);
        gemm_nt<<<g, 256>>>(v_tan, qkv_w, qkv_b, p_vqkv, 512, 1024);
    }

    prep_kernel<<<(32 * 1024) / 8, 256>>>();

    {
        dim3 g(1024 / 128, 1024 / 128, 32);
        score_kernel<<<g, 256>>>(tau, topo_gamma, attn);
    }

    softmax_kernel<<<32 * 1024, 256>>>(attn);

    {
        dim3 g(1, 1024 / 128, 32);
        zgemm_kernel<<<g, 128>>>(attn, zt);
    }
}